// round 15
// baseline (speedup 1.0000x reference)
#include <cuda_runtime.h>
#include <cstdint>

// ---------------------------------------------------------------------------
// BigramHashEmbedding: out[16384, 6144] = table[hash(ids)][.,2048] @ proj^T
// tcgen05 unavailable (harness PTX targets plain sm_103). Path:
//   fused prep kernel (ids dtype detected inline) permutes A (hash-gather)
//   and B into FRAGMENT-PACKED tf32 layout in GMEM -> mma.sync tf32 GEMM,
//   128x128x32, 3-stage cp.async + mbarrier pipeline, mainloop HAND-UNROLLED
//   x3 so all stage indices/parities are compile-time constants.
// PIPELINE RULE (R10/R11): keep >=1 slack stage (PFD < STG); inter-warp waits
// target PREVIOUS-chunk events only; producer wait sits AFTER compute.
// PERSISTENCE RULE (R13): grid-per-tile beats persistent CTAs here.
// The (stage,parity) trace below is byte-identical to the R12 automaton:
//   consumer: chunk i -> stage i%3, parity (i/3)&1
//   producer: chunk j -> stage j%3; group-g parities: e2@ph^1, e0@ph, e1@ph
//
// Packed layouts (float4 units, per 128-row block, per 32-col chunk):
//  A: f4[(mblk*64+chunk)*1024 + pairIdx*16 + slot], slot = (k8*4+lc)^((pairIdx&1)*4)
//  B: f4[(nblk*64+chunk)*1024 + rn*8 + slot],  slot = (kp*4+lc)^((rn&1)*4)
// ---------------------------------------------------------------------------

#define M_TOTAL 16384
#define N_TOTAL 6144
#define K_TOTAL 2048

#define BM 128
#define BN 128
#define BK 32
#define STG 3
#define PFD 2                                 // prefetch distance (< STG: slack!)
#define NCHUNK (K_TOTAL / BK)                 // 64
#define CHUNK_F4 1024                         // 16 KB per operand per chunk
#define STAGE_F4 (2 * CHUNK_F4)               // A + B = 32 KB
#define MBAR_OFF (STG * STAGE_F4 * 16)        // 96 KB: mbarriers live here
#define SMEM_BYTES (MBAR_OFF + 64)

// scratch (device globals -- no allocation allowed)
__device__ __align__(256) float g_h[(size_t)M_TOTAL * K_TOTAL];   // 128 MB packed A
__device__ __align__(256) float g_w[(size_t)N_TOTAL * K_TOTAL];   //  48 MB packed B

// ---------------------------------------------------------------------------
// helpers
// ---------------------------------------------------------------------------
__device__ __forceinline__ uint32_t smem_u32(const void* p) {
    uint32_t a;
    asm("{ .reg .u64 t; cvta.to.shared.u64 t, %1; cvt.u32.u64 %0, t; }" : "=r"(a) : "l"(p));
    return a;
}
__device__ __forceinline__ float f32_tf32(float f) {
    uint32_t r;
    asm("cvt.rna.tf32.f32 %0, %1;" : "=r"(r) : "f"(f));
    return __uint_as_float(r);
}
__device__ __forceinline__ void cp_async16(uint32_t dst, const void* src) {
    asm volatile("cp.async.cg.shared.global [%0], [%1], 16;" :: "r"(dst), "l"(src));
}
__device__ __forceinline__ void stg_cs_v2(float* p, float a, float b) {
    asm volatile("st.global.cs.v2.f32 [%0], {%1, %2};" :: "l"(p), "f"(a), "f"(b) : "memory");
}

#define MBARRIER_INIT(addr, cnt) \
    asm volatile("mbarrier.init.shared.b64 [%0], %1;" :: "r"(addr), "r"(cnt) : "memory")
#define MBARRIER_ARRIVE(addr) \
    asm volatile("mbarrier.arrive.shared.b64 _, [%0];" :: "r"(addr) : "memory")
#define CPASYNC_MBAR_ARRIVE(addr) \
    asm volatile("cp.async.mbarrier.arrive.noinc.shared.b64 [%0];" :: "r"(addr) : "memory")

#define MBARRIER_WAIT_PARITY(mbar_addr, phase_parity) do { \
    uint32_t _mbar = (uint32_t)(mbar_addr); \
    uint32_t _parity = (uint32_t)(phase_parity); \
    uint32_t _done; \
    asm volatile( \
        "{\n\t.reg .pred p;\n\t" \
        "mbarrier.try_wait.parity.shared.b64 p, [%1], %2;\n\t" \
        "selp.b32 %0, 1, 0, p;\n\t}" \
        : "=r"(_done) : "r"(_mbar), "r"(_parity) : "memory"); \
    if (!_done) { \
        asm volatile( \
            "{\n\t.reg .pred P1;\n\t" \
            "WAIT_LOOP_%=:\n\t" \
            "mbarrier.try_wait.parity.shared.b64 P1, [%0], %1;\n\t" \
            "@P1 bra.uni WAIT_DONE_%=;\n\t" \
            "bra.uni WAIT_LOOP_%=;\n\t" \
            "WAIT_DONE_%=:\n\t}" \
            :: "r"(_mbar), "r"(_parity) : "memory"); \
    } \
} while (0)

__device__ __forceinline__ void mma_tf32(float* c, const float4& a, float b0, float b1) {
    asm volatile(
        "mma.sync.aligned.m16n8k8.row.col.f32.tf32.tf32.f32 "
        "{%0,%1,%2,%3}, {%4,%5,%6,%7}, {%8,%9}, {%0,%1,%2,%3};"
        : "+f"(c[0]), "+f"(c[1]), "+f"(c[2]), "+f"(c[3])
        : "r"(__float_as_uint(a.x)), "r"(__float_as_uint(a.y)),
          "r"(__float_as_uint(a.z)), "r"(__float_as_uint(a.w)),
          "r"(__float_as_uint(b0)), "r"(__float_as_uint(b1)));
}

// ---------------------------------------------------------------------------
// Inline ids dtype detection: int64 => odd 32-bit words all zero.
// ---------------------------------------------------------------------------
__device__ __forceinline__ int ids_is64(const void* ids_raw) {
    const int* w = (const int*)ids_raw;
    int all0 = 1;
    #pragma unroll
    for (int i = 1; i < 16; i += 2) all0 &= (w[i] == 0);
    return all0;
}

__device__ __forceinline__ uint32_t hash_m(const void* ids_raw, int m, int is64) {
    uint32_t cur, prev;
    if (is64) {
        const long long* ids = (const long long*)ids_raw;
        cur = (uint32_t)(unsigned long long)ids[m];
        prev = ((m & 4095) == 0) ? 0u : (uint32_t)(unsigned long long)ids[m - 1];
    } else {
        const int* ids = (const int*)ids_raw;
        cur = (uint32_t)ids[m];
        prev = ((m & 4095) == 0) ? 0u : (uint32_t)ids[m - 1];
    }
    // 131072 = 2^17 divides 2^32 -> 32-bit wrap arithmetic is exact mod 2^17
    return (prev * 1000003u + cur) & 131071u;
}

// ---------------------------------------------------------------------------
// Fused prep: blocks [0, 8192) pack A (hash-gather, 2 rows each);
//             blocks [8192, 14336) pack B (1 proj row each).
// ---------------------------------------------------------------------------
__global__ void __launch_bounds__(256) prep_kernel(const void* __restrict__ ids_raw,
                                                   const float* __restrict__ table,
                                                   const float* __restrict__ proj) {
    __shared__ float s0[K_TOTAL], s1[K_TOTAL];
    if (blockIdx.x < 8192) {
        int is64 = ids_is64(ids_raw);
        int mblk = blockIdx.x >> 6;
        int pairIdx = blockIdx.x & 63;
        int r0 = (pairIdx >> 5) * 64 + ((pairIdx >> 3) & 3) * 16 + (pairIdx & 7);
        int m0 = mblk * 128 + r0;
        uint32_t h0 = hash_m(ids_raw, m0, is64);
        uint32_t h1 = hash_m(ids_raw, m0 + 8, is64);
        const float4* t0 = (const float4*)(table + (size_t)h0 * K_TOTAL);
        const float4* t1 = (const float4*)(table + (size_t)h1 * K_TOTAL);
        #pragma unroll 2
        for (int i = threadIdx.x; i < K_TOTAL / 4; i += 256) {
            float4 v = t0[i];
            ((float4*)s0)[i] = make_float4(f32_tf32(v.x), f32_tf32(v.y), f32_tf32(v.z), f32_tf32(v.w));
            float4 w = t1[i];
            ((float4*)s1)[i] = make_float4(f32_tf32(w.x), f32_tf32(w.y), f32_tf32(w.z), f32_tf32(w.w));
        }
        __syncthreads();
        float4* dst = (float4*)g_h + (size_t)mblk * (64 * CHUNK_F4) + pairIdx * 16;
        int sw = (pairIdx & 1) * 4;
        #pragma unroll 4
        for (int o = threadIdx.x; o < 1024; o += 256) {
            int chunk = o >> 4, slot = o & 15;
            int slot0 = slot ^ sw;
            int k8 = slot0 >> 2, lc = slot0 & 3;
            int c0 = chunk * 32 + k8 * 8 + lc;
            dst[(size_t)chunk * CHUNK_F4 + slot] =
                make_float4(s0[c0], s1[c0], s0[c0 + 4], s1[c0 + 4]);
        }
    } else {
        int bid = blockIdx.x - 8192;
        int nblk = bid >> 7;
        int rn = bid & 127;
        int n = nblk * 128 + rn;
        const float4* src = (const float4*)(proj + (size_t)n * K_TOTAL);
        #pragma unroll 2
        for (int i = threadIdx.x; i < K_TOTAL / 4; i += 256) {
            float4 v = src[i];
            ((float4*)s0)[i] = make_float4(f32_tf32(v.x), f32_tf32(v.y), f32_tf32(v.z), f32_tf32(v.w));
        }
        __syncthreads();
        float4* dst = (float4*)g_w + (size_t)nblk * (64 * CHUNK_F4) + rn * 8;
        int sw = (rn & 1) * 4;
        #pragma unroll 2
        for (int o = threadIdx.x; o < 512; o += 256) {
            int chunk = o >> 3, slot = o & 7;
            int slot0 = slot ^ sw;
            int kp = slot0 >> 2, lc = slot0 & 3;
            int c = chunk * 32 + kp * 16 + lc;
            dst[(size_t)chunk * CHUNK_F4 + slot] =
                make_float4(s0[c], s0[c + 4], s0[c + 8], s0[c + 12]);
        }
    }
}

// ---------------------------------------------------------------------------
// Main GEMM: 128x128x32, mma.sync tf32, fragment-packed LDS.128, 3-stage
// cp.async + mbarrier pipeline, mainloop unrolled x3 (constant stages).
// 8 warps = 2(M) x 4(N); warp tile 64x32; 2 CTAs/SM (128-reg cap).
// ---------------------------------------------------------------------------
__global__ void __launch_bounds__(256, 2) gemm_kernel(float* __restrict__ out) {
    extern __shared__ float4 smem[];

    int tid = threadIdx.x;
    int lid = tid & 31;
    int wid = tid >> 5;
    int warp_m = wid & 1;          // 0..1  -> 64 rows each
    int warp_n = wid >> 1;         // 0..3  -> 32 cols each
    int lr = lid >> 2;             // 0..7
    int lc = lid & 3;              // 0..3
    int swz = (lr & 1) * 4;        // phase swizzle baked into packed layout

    int tile_n = blockIdx.x;       // 0..47
    int tile_m = blockIdx.y;       // 0..127

    const char* ag = (const char*)((const float4*)g_h + (size_t)tile_m * (64 * CHUNK_F4));
    const char* bg = (const char*)((const float4*)g_w + (size_t)tile_n * (64 * CHUNK_F4));
    uint32_t sbase = smem_u32(smem);
    uint32_t adst = sbase + (uint32_t)tid * 64u;
    uint32_t bdst = adst + CHUNK_F4 * 16u;
    uint32_t mb = sbase + MBAR_OFF;           // full[s]=mb+8s, empty[s]=mb+24+8s

    if (tid == 0) {
        #pragma unroll
        for (int s = 0; s < STG; s++) {
            MBARRIER_INIT(mb + 8 * s, 256);        // full: all threads' cp.asyncs
            MBARRIER_INIT(mb + 24 + 8 * s, 256);   // empty: all threads arrive
        }
    }
    __syncthreads();

    auto load_chunk = [&](int j, int stage) {
        uint32_t so = (uint32_t)stage * (STAGE_F4 * 16u);
        const char* ap = ag + (size_t)j * (CHUNK_F4 * 16) + tid * 64;
        const char* bp = bg + (size_t)j * (CHUNK_F4 * 16) + tid * 64;
        #pragma unroll
        for (int t = 0; t < 4; t++) cp_async16(adst + so + t * 16, ap + t * 16);
        #pragma unroll
        for (int t = 0; t < 4; t++) cp_async16(bdst + so + t * 16, bp + t * 16);
        CPASYNC_MBAR_ARRIVE(mb + 8 * stage);
    };

    float acc[4][4][4];
    #pragma unroll
    for (int i = 0; i < 4; i++)
        #pragma unroll
        for (int j = 0; j < 4; j++)
            #pragma unroll
            for (int v = 0; v < 4; v++) acc[i][j][v] = 0.0f;

    // prologue: chunks 0,1 (fresh empty bars: parity-1 wait passes immediately)
    #pragma unroll
    for (int j = 0; j < PFD; j++) {
        MBARRIER_WAIT_PARITY(mb + 24 + 8 * j, 1);
        load_chunk(j, j);
    }

    int a_row0 = warp_m * 32;      // + tm*8 + lr
    int b_row0 = warp_n * 32;      // + tn*8 + lr

    // One chunk body; CS (consumer stage), PJS (producer stage) are literals
    // at every call site -> constant SMEM offsets, no stage bookkeeping regs.
    auto chunk_body = [&](int CS, int c_par, int j, int PJS, int p_par, bool do_load) {
        MBARRIER_WAIT_PARITY(mb + 8 * CS, c_par);

        const float4* As = smem + CS * STAGE_F4;
        const float4* Bs = As + CHUNK_F4;

        float4 av[2][4], bv[4];
        #pragma unroll
        for (int tm = 0; tm < 4; tm++)
            av[0][tm] = As[(a_row0 + tm * 8 + lr) * 16 + (lc ^ swz)];
        #pragma unroll
        for (int tn = 0; tn < 4; tn++)
            bv[tn] = Bs[(b_row0 + tn * 8 + lr) * 8 + (lc ^ swz)];

        // k8 = 0: prefetch av(1), MMA av[0] x bv.xy
        #pragma unroll
        for (int tm = 0; tm < 4; tm++)
            av[1][tm] = As[(a_row0 + tm * 8 + lr) * 16 + ((4 + lc) ^ swz)];
        #pragma unroll
        for (int tm = 0; tm < 4; tm++)
            #pragma unroll
            for (int tn = 0; tn < 4; tn++)
                mma_tf32(acc[tm][tn], av[0][tm], bv[tn].x, bv[tn].y);

        // k8 = 1: prefetch av(2), MMA av[1] x bv.zw, reload bv kp=1 (WAR-safe)
        #pragma unroll
        for (int tm = 0; tm < 4; tm++)
            av[0][tm] = As[(a_row0 + tm * 8 + lr) * 16 + ((8 + lc) ^ swz)];
        #pragma unroll
        for (int tm = 0; tm < 4; tm++)
            #pragma unroll
            for (int tn = 0; tn < 4; tn++)
                mma_tf32(acc[tm][tn], av[1][tm], bv[tn].z, bv[tn].w);
        #pragma unroll
        for (int tn = 0; tn < 4; tn++)
            bv[tn] = Bs[(b_row0 + tn * 8 + lr) * 8 + ((4 + lc) ^ swz)];

        // k8 = 2: prefetch av(3), MMA av[0] x bv.xy
        #pragma unroll
        for (int tm = 0; tm < 4; tm++)
            av[1][tm] = As[(a_row0 + tm * 8 + lr) * 16 + ((12 + lc) ^ swz)];
        #pragma unroll
        for (int tm = 0; tm < 4; tm++)
            #pragma unroll
            for (int tn = 0; tn < 4; tn++)
                mma_tf32(acc[tm][tn], av[0][tm], bv[tn].x, bv[tn].y);

        // k8 = 3: MMA av[1] x bv.zw
        #pragma unroll
        for (int tm = 0; tm < 4; tm++)
            #pragma unroll
            for (int tn = 0; tn < 4; tn++)
                mma_tf32(acc[tm][tn], av[1][tm], bv[tn].z, bv[tn].w);

        // release stage CS (all threads)
        MBARRIER_ARRIVE(mb + 24 + 8 * CS);

        // producer: refill chunk j into stage PJS (wait AFTER compute)
        if (do_load) {
            MBARRIER_WAIT_PARITY(mb + 24 + 8 * PJS, p_par);
            load_chunk(j, PJS);
        }
    };

    // 64 chunks = 21 unrolled groups of 3 + 1 tail. (stage,parity) trace is
    // identical to the R12 rolling automaton (verified chunk-by-chunk).
    int ph = 0;
    for (int g = 0; g < 21; g++) {
        int j0 = 3 * g + 2;
        chunk_body(0, ph, j0,     2, ph ^ 1, true);
        chunk_body(1, ph, j0 + 1, 0, ph,     true);
        chunk_body(2, ph, j0 + 2, 1, ph,     g < 20);   // j=64 skipped at g=20
        ph ^= 1;
    }
    // tail: chunk 63 -> stage 0, parity (63/3)&1 = 1 = ph; no producer
    chunk_body(0, ph, 0, 0, 0, false);

    // --- epilogue: streaming stores (evict-first: don't pollute L2 for A/B) ---
    #pragma unroll
    for (int tm = 0; tm < 4; tm++) {
        int r0 = tile_m * BM + warp_m * 64 + tm * 16 + lr;
        #pragma unroll
        for (int tn = 0; tn < 4; tn++) {
            int c0 = tile_n * BN + warp_n * 32 + tn * 8 + lc * 2;
            float* p0 = out + (size_t)r0 * N_TOTAL + c0;
            float* p1 = out + (size_t)(r0 + 8) * N_TOTAL + c0;
            stg_cs_v2(p0, acc[tm][tn][0], acc[tm][tn][1]);
            stg_cs_v2(p1, acc[tm][tn][2], acc[tm][tn][3]);
        }
    }
}

// ---------------------------------------------------------------------------
extern "C" void kernel_launch(void* const* d_in, const int* in_sizes, int n_in,
                              void* d_out, int out_size) {
    // Resolve inputs BY SIZE (robust to ordering):
    //   input_ids: 16384 (int32 or int64, detected inline on device)
    //   table: 268435456 fp32; proj_w: 12582912 fp32
    const void* ids = nullptr;
    const float* table = nullptr;
    const float* proj = nullptr;
    for (int i = 0; i < n_in; i++) {
        if (in_sizes[i] == 16384) ids = d_in[i];
        else if (in_sizes[i] == 268435456) table = (const float*)d_in[i];
        else if (in_sizes[i] == 12582912) proj = (const float*)d_in[i];
    }
    float* out = (float*)d_out;                         // fp32 [4,4096,6144]
    (void)out_size;

    cudaFuncSetAttribute(gemm_kernel,
                         cudaFuncAttributeMaxDynamicSharedMemorySize, SMEM_BYTES);

    prep_kernel<<<8192 + 6144, 256>>>(ids, table, proj);

    dim3 grid(N_TOTAL / BN, M_TOTAL / BM);   // (48, 128) -- x fastest => A-tile L2 reuse
    gemm_kernel<<<grid, 256, SMEM_BYTES>>>(out);
}

// round 16
// speedup vs baseline: 1.0817x; 1.0817x over previous
#include <cuda_runtime.h>
#include <cstdint>

// ---------------------------------------------------------------------------
// BigramHashEmbedding: out[16384, 6144] = table[hash(ids)][.,2048] @ proj^T
// tcgen05 unavailable (harness PTX targets plain sm_103). Path:
//   fused prep kernel (ids dtype detected inline) permutes A (hash-gather)
//   and B into FRAGMENT-PACKED tf32 layout in GMEM -> mma.sync tf32 GEMM,
//   128x128x32, 3-stage cp.async + mbarrier pipeline (R14 rolling loop),
//   warp-leader empty arrivals (count 8).
// PIPELINE RULE (R10/R11): keep >=1 slack stage (PFD < STG); inter-warp waits
// target PREVIOUS-chunk events only; producer wait sits AFTER compute.
// PERSISTENCE RULE (R13): grid-per-tile beats persistent CTAs here.
// CODE-SIZE RULE (R15): mainloop body is near the 6KB L0 I$ limit -- do not
// unroll across chunks.
//
// Packed layouts (float4 units, per 128-row block, per 32-col chunk):
//  A: f4[(mblk*64+chunk)*1024 + pairIdx*16 + slot], slot = (k8*4+lc)^((pairIdx&1)*4)
//  B: f4[(nblk*64+chunk)*1024 + rn*8 + slot],  slot = (kp*4+lc)^((rn&1)*4)
// ---------------------------------------------------------------------------

#define M_TOTAL 16384
#define N_TOTAL 6144
#define K_TOTAL 2048

#define BM 128
#define BN 128
#define BK 32
#define STG 3
#define PFD 2                                 // prefetch distance (< STG: slack!)
#define NCHUNK (K_TOTAL / BK)                 // 64
#define CHUNK_F4 1024                         // 16 KB per operand per chunk
#define STAGE_F4 (2 * CHUNK_F4)               // A + B = 32 KB
#define MBAR_OFF (STG * STAGE_F4 * 16)        // 96 KB: mbarriers live here
#define SMEM_BYTES (MBAR_OFF + 64)

// scratch (device globals -- no allocation allowed)
__device__ __align__(256) float g_h[(size_t)M_TOTAL * K_TOTAL];   // 128 MB packed A
__device__ __align__(256) float g_w[(size_t)N_TOTAL * K_TOTAL];   //  48 MB packed B

// ---------------------------------------------------------------------------
// helpers
// ---------------------------------------------------------------------------
__device__ __forceinline__ uint32_t smem_u32(const void* p) {
    uint32_t a;
    asm("{ .reg .u64 t; cvta.to.shared.u64 t, %1; cvt.u32.u64 %0, t; }" : "=r"(a) : "l"(p));
    return a;
}
__device__ __forceinline__ float f32_tf32(float f) {
    uint32_t r;
    asm("cvt.rna.tf32.f32 %0, %1;" : "=r"(r) : "f"(f));
    return __uint_as_float(r);
}
__device__ __forceinline__ void cp_async16(uint32_t dst, const void* src) {
    asm volatile("cp.async.cg.shared.global [%0], [%1], 16;" :: "r"(dst), "l"(src));
}
__device__ __forceinline__ void stg_cs_v2(float* p, float a, float b) {
    asm volatile("st.global.cs.v2.f32 [%0], {%1, %2};" :: "l"(p), "f"(a), "f"(b) : "memory");
}

#define MBARRIER_INIT(addr, cnt) \
    asm volatile("mbarrier.init.shared.b64 [%0], %1;" :: "r"(addr), "r"(cnt) : "memory")
#define MBARRIER_ARRIVE(addr) \
    asm volatile("mbarrier.arrive.shared.b64 _, [%0];" :: "r"(addr) : "memory")
#define CPASYNC_MBAR_ARRIVE(addr) \
    asm volatile("cp.async.mbarrier.arrive.noinc.shared.b64 [%0];" :: "r"(addr) : "memory")

#define MBARRIER_WAIT_PARITY(mbar_addr, phase_parity) do { \
    uint32_t _mbar = (uint32_t)(mbar_addr); \
    uint32_t _parity = (uint32_t)(phase_parity); \
    uint32_t _done; \
    asm volatile( \
        "{\n\t.reg .pred p;\n\t" \
        "mbarrier.try_wait.parity.shared.b64 p, [%1], %2;\n\t" \
        "selp.b32 %0, 1, 0, p;\n\t}" \
        : "=r"(_done) : "r"(_mbar), "r"(_parity) : "memory"); \
    if (!_done) { \
        asm volatile( \
            "{\n\t.reg .pred P1;\n\t" \
            "WAIT_LOOP_%=:\n\t" \
            "mbarrier.try_wait.parity.shared.b64 P1, [%0], %1;\n\t" \
            "@P1 bra.uni WAIT_DONE_%=;\n\t" \
            "bra.uni WAIT_LOOP_%=;\n\t" \
            "WAIT_DONE_%=:\n\t}" \
            :: "r"(_mbar), "r"(_parity) : "memory"); \
    } \
} while (0)

__device__ __forceinline__ void mma_tf32(float* c, const float4& a, float b0, float b1) {
    asm volatile(
        "mma.sync.aligned.m16n8k8.row.col.f32.tf32.tf32.f32 "
        "{%0,%1,%2,%3}, {%4,%5,%6,%7}, {%8,%9}, {%0,%1,%2,%3};"
        : "+f"(c[0]), "+f"(c[1]), "+f"(c[2]), "+f"(c[3])
        : "r"(__float_as_uint(a.x)), "r"(__float_as_uint(a.y)),
          "r"(__float_as_uint(a.z)), "r"(__float_as_uint(a.w)),
          "r"(__float_as_uint(b0)), "r"(__float_as_uint(b1)));
}

// ---------------------------------------------------------------------------
// Inline ids dtype detection: int64 => odd 32-bit words all zero.
// ---------------------------------------------------------------------------
__device__ __forceinline__ int ids_is64(const void* ids_raw) {
    const int* w = (const int*)ids_raw;
    int all0 = 1;
    #pragma unroll
    for (int i = 1; i < 16; i += 2) all0 &= (w[i] == 0);
    return all0;
}

__device__ __forceinline__ uint32_t hash_m(const void* ids_raw, int m, int is64) {
    uint32_t cur, prev;
    if (is64) {
        const long long* ids = (const long long*)ids_raw;
        cur = (uint32_t)(unsigned long long)ids[m];
        prev = ((m & 4095) == 0) ? 0u : (uint32_t)(unsigned long long)ids[m - 1];
    } else {
        const int* ids = (const int*)ids_raw;
        cur = (uint32_t)ids[m];
        prev = ((m & 4095) == 0) ? 0u : (uint32_t)ids[m - 1];
    }
    // 131072 = 2^17 divides 2^32 -> 32-bit wrap arithmetic is exact mod 2^17
    return (prev * 1000003u + cur) & 131071u;
}

// ---------------------------------------------------------------------------
// Fused prep: blocks [0, 8192) pack A (hash-gather, 2 rows each);
//             blocks [8192, 14336) pack B (1 proj row each).
// ---------------------------------------------------------------------------
__global__ void __launch_bounds__(256) prep_kernel(const void* __restrict__ ids_raw,
                                                   const float* __restrict__ table,
                                                   const float* __restrict__ proj) {
    __shared__ float s0[K_TOTAL], s1[K_TOTAL];
    if (blockIdx.x < 8192) {
        int is64 = ids_is64(ids_raw);
        int mblk = blockIdx.x >> 6;
        int pairIdx = blockIdx.x & 63;
        int r0 = (pairIdx >> 5) * 64 + ((pairIdx >> 3) & 3) * 16 + (pairIdx & 7);
        int m0 = mblk * 128 + r0;
        uint32_t h0 = hash_m(ids_raw, m0, is64);
        uint32_t h1 = hash_m(ids_raw, m0 + 8, is64);
        const float4* t0 = (const float4*)(table + (size_t)h0 * K_TOTAL);
        const float4* t1 = (const float4*)(table + (size_t)h1 * K_TOTAL);
        #pragma unroll 2
        for (int i = threadIdx.x; i < K_TOTAL / 4; i += 256) {
            float4 v = t0[i];
            ((float4*)s0)[i] = make_float4(f32_tf32(v.x), f32_tf32(v.y), f32_tf32(v.z), f32_tf32(v.w));
            float4 w = t1[i];
            ((float4*)s1)[i] = make_float4(f32_tf32(w.x), f32_tf32(w.y), f32_tf32(w.z), f32_tf32(w.w));
        }
        __syncthreads();
        float4* dst = (float4*)g_h + (size_t)mblk * (64 * CHUNK_F4) + pairIdx * 16;
        int sw = (pairIdx & 1) * 4;
        #pragma unroll 4
        for (int o = threadIdx.x; o < 1024; o += 256) {
            int chunk = o >> 4, slot = o & 15;
            int slot0 = slot ^ sw;
            int k8 = slot0 >> 2, lc = slot0 & 3;
            int c0 = chunk * 32 + k8 * 8 + lc;
            dst[(size_t)chunk * CHUNK_F4 + slot] =
                make_float4(s0[c0], s1[c0], s0[c0 + 4], s1[c0 + 4]);
        }
    } else {
        int bid = blockIdx.x - 8192;
        int nblk = bid >> 7;
        int rn = bid & 127;
        int n = nblk * 128 + rn;
        const float4* src = (const float4*)(proj + (size_t)n * K_TOTAL);
        #pragma unroll 2
        for (int i = threadIdx.x; i < K_TOTAL / 4; i += 256) {
            float4 v = src[i];
            ((float4*)s0)[i] = make_float4(f32_tf32(v.x), f32_tf32(v.y), f32_tf32(v.z), f32_tf32(v.w));
        }
        __syncthreads();
        float4* dst = (float4*)g_w + (size_t)nblk * (64 * CHUNK_F4) + rn * 8;
        int sw = (rn & 1) * 4;
        #pragma unroll 2
        for (int o = threadIdx.x; o < 512; o += 256) {
            int chunk = o >> 3, slot = o & 7;
            int slot0 = slot ^ sw;
            int kp = slot0 >> 2, lc = slot0 & 3;
            int c = chunk * 32 + kp * 16 + lc;
            dst[(size_t)chunk * CHUNK_F4 + slot] =
                make_float4(s0[c], s0[c + 4], s0[c + 8], s0[c + 12]);
        }
    }
}

// ---------------------------------------------------------------------------
// Main GEMM (R14 rolling loop): 128x128x32, mma.sync tf32, fragment-packed
// LDS.128, 3-stage cp.async + mbarrier pipeline; leader-only empty arrivals.
// 8 warps = 2(M) x 4(N); warp tile 64x32; 2 CTAs/SM (128-reg cap).
// ---------------------------------------------------------------------------
__global__ void __launch_bounds__(256, 2) gemm_kernel(float* __restrict__ out) {
    extern __shared__ float4 smem[];

    int tid = threadIdx.x;
    int lid = tid & 31;
    int wid = tid >> 5;
    int warp_m = wid & 1;          // 0..1  -> 64 rows each
    int warp_n = wid >> 1;         // 0..3  -> 32 cols each
    int lr = lid >> 2;             // 0..7
    int lc = lid & 3;              // 0..3
    int swz = (lr & 1) * 4;        // phase swizzle baked into packed layout

    int tile_n = blockIdx.x;       // 0..47
    int tile_m = blockIdx.y;       // 0..127

    const char* ag = (const char*)((const float4*)g_h + (size_t)tile_m * (64 * CHUNK_F4));
    const char* bg = (const char*)((const float4*)g_w + (size_t)tile_n * (64 * CHUNK_F4));
    uint32_t sbase = smem_u32(smem);
    uint32_t adst = sbase + (uint32_t)tid * 64u;
    uint32_t bdst = adst + CHUNK_F4 * 16u;
    uint32_t mb = sbase + MBAR_OFF;           // full[s]=mb+8s, empty[s]=mb+24+8s

    if (tid == 0) {
        #pragma unroll
        for (int s = 0; s < STG; s++) {
            MBARRIER_INIT(mb + 8 * s, 256);        // full: all threads' cp.asyncs
            MBARRIER_INIT(mb + 24 + 8 * s, 8);     // empty: warp leaders only
        }
    }
    __syncthreads();

    auto load_chunk = [&](int j, int stage) {
        uint32_t so = (uint32_t)stage * (STAGE_F4 * 16u);
        const char* ap = ag + (size_t)j * (CHUNK_F4 * 16) + tid * 64;
        const char* bp = bg + (size_t)j * (CHUNK_F4 * 16) + tid * 64;
        #pragma unroll
        for (int t = 0; t < 4; t++) cp_async16(adst + so + t * 16, ap + t * 16);
        #pragma unroll
        for (int t = 0; t < 4; t++) cp_async16(bdst + so + t * 16, bp + t * 16);
        CPASYNC_MBAR_ARRIVE(mb + 8 * stage);
    };

    float acc[4][4][4];
    #pragma unroll
    for (int i = 0; i < 4; i++)
        #pragma unroll
        for (int j = 0; j < 4; j++)
            #pragma unroll
            for (int v = 0; v < 4; v++) acc[i][j][v] = 0.0f;

    // prologue: chunks 0,1 (fresh empty bars: parity-1 wait passes immediately)
    #pragma unroll
    for (int j = 0; j < PFD; j++) {
        MBARRIER_WAIT_PARITY(mb + 24 + 8 * j, 1);
        load_chunk(j, j);
    }

    int a_row0 = warp_m * 32;      // + tm*8 + lr
    int b_row0 = warp_n * 32;      // + tn*8 + lr

    int cs = 0, cpar = 0;                            // consumer stage/parity
    int js = PFD % STG, jpar = (PFD < STG) ? 1 : 0;  // producer stage/parity

    for (int i = 0; i < NCHUNK; i++) {
        // ---- consumer: wait chunk i resident (per-warp, previous-chunk event) ----
        MBARRIER_WAIT_PARITY(mb + 8 * cs, cpar);

        const float4* As = smem + cs * STAGE_F4;
        const float4* Bs = As + CHUNK_F4;

        // av double-buffered, bv single-buffered (reloaded after k8=1 MMAs).
        float4 av[2][4], bv[4];
        #pragma unroll
        for (int tm = 0; tm < 4; tm++)
            av[0][tm] = As[(a_row0 + tm * 8 + lr) * 16 + (lc ^ swz)];
        #pragma unroll
        for (int tn = 0; tn < 4; tn++)
            bv[tn] = Bs[(b_row0 + tn * 8 + lr) * 8 + (lc ^ swz)];

        // k8 = 0: prefetch av(1), MMA av[0] x bv.xy
        #pragma unroll
        for (int tm = 0; tm < 4; tm++)
            av[1][tm] = As[(a_row0 + tm * 8 + lr) * 16 + ((4 + lc) ^ swz)];
        #pragma unroll
        for (int tm = 0; tm < 4; tm++)
            #pragma unroll
            for (int tn = 0; tn < 4; tn++)
                mma_tf32(acc[tm][tn], av[0][tm], bv[tn].x, bv[tn].y);

        // k8 = 1: prefetch av(2), MMA av[1] x bv.zw, reload bv kp=1 (WAR-safe)
        #pragma unroll
        for (int tm = 0; tm < 4; tm++)
            av[0][tm] = As[(a_row0 + tm * 8 + lr) * 16 + ((8 + lc) ^ swz)];
        #pragma unroll
        for (int tm = 0; tm < 4; tm++)
            #pragma unroll
            for (int tn = 0; tn < 4; tn++)
                mma_tf32(acc[tm][tn], av[1][tm], bv[tn].z, bv[tn].w);
        #pragma unroll
        for (int tn = 0; tn < 4; tn++)
            bv[tn] = Bs[(b_row0 + tn * 8 + lr) * 8 + ((4 + lc) ^ swz)];

        // k8 = 2: prefetch av(3), MMA av[0] x bv.xy
        #pragma unroll
        for (int tm = 0; tm < 4; tm++)
            av[1][tm] = As[(a_row0 + tm * 8 + lr) * 16 + ((12 + lc) ^ swz)];
        #pragma unroll
        for (int tm = 0; tm < 4; tm++)
            #pragma unroll
            for (int tn = 0; tn < 4; tn++)
                mma_tf32(acc[tm][tn], av[0][tm], bv[tn].x, bv[tn].y);

        // k8 = 3: MMA av[1] x bv.zw
        #pragma unroll
        for (int tm = 0; tm < 4; tm++)
            #pragma unroll
            for (int tn = 0; tn < 4; tn++)
                mma_tf32(acc[tm][tn], av[1][tm], bv[tn].z, bv[tn].w);

        // ---- release stage cs: warp leaders only (warp-synchronous LDS done) ----
        if (lid == 0) MBARRIER_ARRIVE(mb + 24 + 8 * cs);
        if (++cs == STG) { cs = 0; cpar ^= 1; }

        // ---- producer: refill chunk i+PFD (wait AFTER compute; slack stage) ----
        int j = i + PFD;
        if (j < NCHUNK) {
            MBARRIER_WAIT_PARITY(mb + 24 + 8 * js, jpar);
            load_chunk(j, js);
            if (++js == STG) { js = 0; jpar ^= 1; }
        }
    }

    // --- epilogue: streaming stores (evict-first: don't pollute L2 for A/B) ---
    #pragma unroll
    for (int tm = 0; tm < 4; tm++) {
        int r0 = tile_m * BM + warp_m * 64 + tm * 16 + lr;
        #pragma unroll
        for (int tn = 0; tn < 4; tn++) {
            int c0 = tile_n * BN + warp_n * 32 + tn * 8 + lc * 2;
            float* p0 = out + (size_t)r0 * N_TOTAL + c0;
            float* p1 = out + (size_t)(r0 + 8) * N_TOTAL + c0;
            stg_cs_v2(p0, acc[tm][tn][0], acc[tm][tn][1]);
            stg_cs_v2(p1, acc[tm][tn][2], acc[tm][tn][3]);
        }
    }
}

// ---------------------------------------------------------------------------
extern "C" void kernel_launch(void* const* d_in, const int* in_sizes, int n_in,
                              void* d_out, int out_size) {
    // Resolve inputs BY SIZE (robust to ordering):
    //   input_ids: 16384 (int32 or int64, detected inline on device)
    //   table: 268435456 fp32; proj_w: 12582912 fp32
    const void* ids = nullptr;
    const float* table = nullptr;
    const float* proj = nullptr;
    for (int i = 0; i < n_in; i++) {
        if (in_sizes[i] == 16384) ids = d_in[i];
        else if (in_sizes[i] == 268435456) table = (const float*)d_in[i];
        else if (in_sizes[i] == 12582912) proj = (const float*)d_in[i];
    }
    float* out = (float*)d_out;                         // fp32 [4,4096,6144]
    (void)out_size;

    cudaFuncSetAttribute(gemm_kernel,
                         cudaFuncAttributeMaxDynamicSharedMemorySize, SMEM_BYTES);

    prep_kernel<<<8192 + 6144, 256>>>(ids, table, proj);

    dim3 grid(N_TOTAL / BN, M_TOTAL / BM);   // (48, 128) -- x fastest => A-tile L2 reuse
    gemm_kernel<<<grid, 256, SMEM_BYTES>>>(out);
}